// round 1
// baseline (speedup 1.0000x reference)
#include <cuda_runtime.h>
#include <stdint.h>

// Problem constants
#define B 8
#define H 12
#define L 1024
#define D 768
#define KSEL 512
#define HL (H * L)            // 12288 rows per batch in the score tensor
#define SPLITS 96
#define ROWS_PER_SPLIT (HL / SPLITS)   // 128

// Scratch (device globals: no allocation allowed in kernel_launch)
__device__ float g_partial[B * SPLITS * L];   // 3 MB
__device__ int   g_selidx[B * KSEL];

// ---------------------------------------------------------------------------
// Kernel A: column sums of scores over (h, i), split 96 ways for parallelism.
// scores layout [B, H, L, L] with j (last dim) contiguous -> coalesced loads.
// grid (B, SPLITS), block 256; each thread accumulates 4 j positions.
// ---------------------------------------------------------------------------
__global__ void __launch_bounds__(256) colsum_kernel(
    const float* __restrict__ scores, float* __restrict__ partial)
{
    const int b = blockIdx.x;
    const int s = blockIdx.y;
    const int t = threadIdx.x;

    const float* base = scores + ((size_t)b * HL + (size_t)s * ROWS_PER_SPLIT) * L;

    float acc0 = 0.f, acc1 = 0.f, acc2 = 0.f, acc3 = 0.f;
#pragma unroll 4
    for (int r = 0; r < ROWS_PER_SPLIT; ++r) {
        const float* row = base + (size_t)r * L;
        acc0 += row[t];
        acc1 += row[t + 256];
        acc2 += row[t + 512];
        acc3 += row[t + 768];
    }

    float* out = partial + ((size_t)b * SPLITS + s) * L;
    out[t]       = acc0;
    out[t + 256] = acc1;
    out[t + 512] = acc2;
    out[t + 768] = acc3;
}

// ---------------------------------------------------------------------------
// Kernel B: per batch, reduce partials -> importance; select top-512 via
// rank counting with top_k tie-break (lower index wins); compact indices
// in ascending index order (== sorted top-k indices).
// grid (B), block 1024.
// ---------------------------------------------------------------------------
__global__ void __launch_bounds__(1024) select_kernel(
    const float* __restrict__ partial, int* __restrict__ selidx)
{
    const int b = blockIdx.x;
    const int j = threadIdx.x;

    __shared__ float v[L];
    __shared__ unsigned char sel[L];

    // Reduce partials for column j
    float sum = 0.f;
    const float* p = partial + (size_t)b * SPLITS * L + j;
#pragma unroll 8
    for (int s = 0; s < SPLITS; ++s) sum += p[(size_t)s * L];
    v[j] = sum;
    __syncthreads();

    // Descending rank with tie-break: element j' beats j if v[j'] > v[j],
    // or equal value with smaller index (top_k preference).
    const float mv = sum;
    int cnt = 0;
#pragma unroll 8
    for (int jj = 0; jj < L; ++jj) {
        const float o = v[jj];
        cnt += (o > mv) || (o == mv && jj < j);
    }
    const bool selected = (cnt < KSEL);
    sel[j] = selected ? 1 : 0;
    __syncthreads();

    // Output position = number of selected with smaller index (ascending order)
    if (selected) {
        int pos = 0;
#pragma unroll 8
        for (int jj = 0; jj < j; ++jj) pos += sel[jj];
        selidx[b * KSEL + pos] = j;
    }
}

// ---------------------------------------------------------------------------
// Kernel C: gather rows into output. Row 0 = class token (j=0), rows 1..512 =
// selected tokens. Also writes the final attention mask tail of d_out.
// grid (513, B), block 192 (one float4 per thread per row: 768/4 = 192).
// ---------------------------------------------------------------------------
__global__ void __launch_bounds__(192) gather_kernel(
    const float* __restrict__ hs, const float* __restrict__ mask,
    const int* __restrict__ selidx, float* __restrict__ out)
{
    const int r = blockIdx.x;           // 0..512
    const int b = blockIdx.y;
    const int j = (r == 0) ? 0 : selidx[b * KSEL + (r - 1)];

    const float4* src = (const float4*)(hs + ((size_t)b * L + j) * D);
    float4* dst = (float4*)(out + ((size_t)b * (KSEL + 1) + r) * D);
    dst[threadIdx.x] = src[threadIdx.x];

    if (threadIdx.x == 0) {
        const float m = (r == 0) ? 0.f : mask[(size_t)b * L + j];
        out[(size_t)B * (KSEL + 1) * D + (size_t)b * (KSEL + 1) + r] = m;
    }
}

// ---------------------------------------------------------------------------
extern "C" void kernel_launch(void* const* d_in, const int* in_sizes, int n_in,
                              void* d_out, int out_size)
{
    const float* hidden = (const float*)d_in[0];   // [B, L, D]
    const float* amask  = (const float*)d_in[1];   // [B, 1, 1, L]
    const float* scores = (const float*)d_in[2];   // [B, H, L, L]
    float* out = (float*)d_out;                    // tokens then mask, f32

    float* d_partial;
    int*   d_selidx;
    cudaGetSymbolAddress((void**)&d_partial, g_partial);
    cudaGetSymbolAddress((void**)&d_selidx,  g_selidx);

    dim3 gridA(B, SPLITS);
    colsum_kernel<<<gridA, 256>>>(scores, d_partial);

    select_kernel<<<B, 1024>>>(d_partial, d_selidx);

    dim3 gridC(KSEL + 1, B);
    gather_kernel<<<gridC, 192>>>(hidden, amask, d_selidx, out);
}

// round 2
// speedup vs baseline: 1.4642x; 1.4642x over previous
#include <cuda_runtime.h>
#include <stdint.h>

// Problem constants
#define B 8
#define H 12
#define L 1024
#define D 768
#define KSEL 512
#define HL (H * L)                       // 12288 rows per batch
#define SPLITS 192
#define ROWS_PER_SPLIT (HL / SPLITS)     // 64
#define L4 (L / 4)                       // 256 float4 per row

// Scratch (device globals: allocation is forbidden in kernel_launch)
__device__ float         g_partial[B * SPLITS * L];   // ~6.3 MB
__device__ float         g_imp[B * L];
__device__ unsigned char g_flags[B * L];
__device__ int           g_selidx[B * KSEL];

// ---------------------------------------------------------------------------
// Kernel A: column sums over (h, i) rows, 192-way split, float4 streaming.
// grid (B, SPLITS), block 256. Each thread owns one float4 column group.
// ---------------------------------------------------------------------------
__global__ void __launch_bounds__(256) colsum_kernel(
    const float4* __restrict__ scores4, float4* __restrict__ partial4)
{
    const int b = blockIdx.x;
    const int s = blockIdx.y;
    const int t = threadIdx.x;

    const float4* base =
        scores4 + ((size_t)b * HL + (size_t)s * ROWS_PER_SPLIT) * L4 + t;

    float4 acc = make_float4(0.f, 0.f, 0.f, 0.f);
#pragma unroll 8
    for (int r = 0; r < ROWS_PER_SPLIT; ++r) {
        const float4 x = __ldcs(base + (size_t)r * L4);
        acc.x += x.x; acc.y += x.y; acc.z += x.z; acc.w += x.w;
    }

    partial4[((size_t)b * SPLITS + s) * L4 + t] = acc;
}

// ---------------------------------------------------------------------------
// Kernel B1: reduce 192 partials -> importance[B][L].
// grid (B, 8), block 128. One j per thread; coalesced per split iteration.
// ---------------------------------------------------------------------------
__global__ void __launch_bounds__(128) reduce_kernel(
    const float* __restrict__ partial, float* __restrict__ imp)
{
    const int b = blockIdx.x;
    const int j = blockIdx.y * 128 + threadIdx.x;

    const float* p = partial + (size_t)b * SPLITS * L + j;
    float sum = 0.f;
#pragma unroll 16
    for (int s = 0; s < SPLITS; ++s) sum += p[(size_t)s * L];
    imp[b * L + j] = sum;
}

// ---------------------------------------------------------------------------
// Kernel B2a: descending rank via counting, distributed over 64 blocks.
// grid (B, 8), block 128; each block ranks 128 j's against all L values.
// Tie-break identical to jax top_k: equal value -> smaller index wins.
// ---------------------------------------------------------------------------
__global__ void __launch_bounds__(128) rank_kernel(
    const float* __restrict__ imp, unsigned char* __restrict__ flags)
{
    const int b = blockIdx.x;
    const int j = blockIdx.y * 128 + threadIdx.x;

    __shared__ float v[L];
    for (int i = threadIdx.x; i < L; i += 128) v[i] = imp[b * L + i];
    __syncthreads();

    const float mv = v[j];
    const float4* v4 = (const float4*)v;
    int cnt = 0;
#pragma unroll 8
    for (int q = 0; q < L4; ++q) {
        const float4 x = v4[q];
        const int i0 = 4 * q;
        cnt += (x.x > mv) || (x.x == mv && (i0 + 0) < j);
        cnt += (x.y > mv) || (x.y == mv && (i0 + 1) < j);
        cnt += (x.z > mv) || (x.z == mv && (i0 + 2) < j);
        cnt += (x.w > mv) || (x.w == mv && (i0 + 3) < j);
    }
    flags[b * L + j] = (cnt < KSEL) ? 1 : 0;
}

// ---------------------------------------------------------------------------
// Kernel B2b: compact selected indices in ascending order via ballot scan.
// grid (B), block 1024.
// ---------------------------------------------------------------------------
__global__ void __launch_bounds__(1024) compact_kernel(
    const unsigned char* __restrict__ flags, int* __restrict__ selidx)
{
    const int b = blockIdx.x;
    const int j = threadIdx.x;
    const int wid = j >> 5;
    const int lane = j & 31;

    const bool s = flags[b * L + j] != 0;
    const unsigned mask = __ballot_sync(0xffffffffu, s);

    __shared__ int wcnt[32];
    __shared__ int woff[32];
    if (lane == 0) wcnt[wid] = __popc(mask);
    __syncthreads();
    if (wid == 0) {
        int val = wcnt[lane];
        int orig = val;
#pragma unroll
        for (int d = 1; d < 32; d <<= 1) {
            const int n = __shfl_up_sync(0xffffffffu, val, d);
            if (lane >= d) val += n;
        }
        woff[lane] = val - orig;   // exclusive prefix
    }
    __syncthreads();

    if (s) {
        const int pos = woff[wid] + __popc(mask & ((1u << lane) - 1u));
        selidx[b * KSEL + pos] = j;
    }
}

// ---------------------------------------------------------------------------
// Kernel C: gather rows + mask into output. Row 0 = class token (j=0).
// grid (513, B), block 192 (768/4 float4 per row).
// ---------------------------------------------------------------------------
__global__ void __launch_bounds__(192) gather_kernel(
    const float* __restrict__ hs, const float* __restrict__ mask,
    const int* __restrict__ selidx, float* __restrict__ out)
{
    const int r = blockIdx.x;           // 0..512
    const int b = blockIdx.y;
    const int j = (r == 0) ? 0 : selidx[b * KSEL + (r - 1)];

    const float4* src = (const float4*)(hs + ((size_t)b * L + j) * D);
    float4* dst = (float4*)(out + ((size_t)b * (KSEL + 1) + r) * D);
    dst[threadIdx.x] = src[threadIdx.x];

    if (threadIdx.x == 0) {
        const float m = (r == 0) ? 0.f : mask[(size_t)b * L + j];
        out[(size_t)B * (KSEL + 1) * D + (size_t)b * (KSEL + 1) + r] = m;
    }
}

// ---------------------------------------------------------------------------
extern "C" void kernel_launch(void* const* d_in, const int* in_sizes, int n_in,
                              void* d_out, int out_size)
{
    const float* hidden = (const float*)d_in[0];   // [B, L, D]
    const float* amask  = (const float*)d_in[1];   // [B, 1, 1, L]
    const float* scores = (const float*)d_in[2];   // [B, H, L, L]
    float* out = (float*)d_out;                    // tokens then mask, f32

    float*         d_partial;
    float*         d_imp;
    unsigned char* d_flags;
    int*           d_selidx;
    cudaGetSymbolAddress((void**)&d_partial, g_partial);
    cudaGetSymbolAddress((void**)&d_imp,     g_imp);
    cudaGetSymbolAddress((void**)&d_flags,   g_flags);
    cudaGetSymbolAddress((void**)&d_selidx,  g_selidx);

    dim3 gridA(B, SPLITS);
    colsum_kernel<<<gridA, 256>>>((const float4*)scores, (float4*)d_partial);

    dim3 gridB1(B, 8);
    reduce_kernel<<<gridB1, 128>>>(d_partial, d_imp);

    dim3 gridB2(B, 8);
    rank_kernel<<<gridB2, 128>>>(d_imp, d_flags);

    compact_kernel<<<B, 1024>>>(d_flags, d_selidx);

    dim3 gridC(KSEL + 1, B);
    gather_kernel<<<gridC, 192>>>(hidden, amask, d_selidx, out);
}

// round 3
// speedup vs baseline: 1.6762x; 1.1448x over previous
#include <cuda_runtime.h>
#include <stdint.h>

// Problem constants
#define B 8
#define H 12
#define L 1024
#define D 768
#define KSEL 512
#define HL (H * L)                       // 12288 rows per batch
#define SPLITS 96
#define ROWS_PER_SPLIT (HL / SPLITS)     // 128
#define L4 (L / 4)                       // 256 float4 per row

// Scratch (device globals: allocation is forbidden in kernel_launch)
__device__ float g_partial[B * SPLITS * L];   // ~3.1 MB
__device__ int   g_selidx[B * KSEL];

// ---------------------------------------------------------------------------
// Kernel A: column sums over (h, i) rows, 96-way split, float4 streaming.
// grid (B, SPLITS), block 256. Each thread owns one float4 column group.
// Unroll 16 => 16 independent LDG.128 in flight per thread.
// ---------------------------------------------------------------------------
__global__ void __launch_bounds__(256) colsum_kernel(
    const float4* __restrict__ scores4, float4* __restrict__ partial4)
{
    const int b = blockIdx.x;
    const int s = blockIdx.y;
    const int t = threadIdx.x;

    const float4* base =
        scores4 + ((size_t)b * HL + (size_t)s * ROWS_PER_SPLIT) * L4 + t;

    float4 acc = make_float4(0.f, 0.f, 0.f, 0.f);
#pragma unroll 16
    for (int r = 0; r < ROWS_PER_SPLIT; ++r) {
        const float4 x = __ldcs(base + (size_t)r * L4);
        acc.x += x.x; acc.y += x.y; acc.z += x.z; acc.w += x.w;
    }

    partial4[((size_t)b * SPLITS + s) * L4 + t] = acc;
}

// ---------------------------------------------------------------------------
// Kernel S: fused reduce + radix top-K select + compact.
// grid (B), block 1024. One thread per token column.
//   1) reduce 96 partials -> importance (register)
//   2) monotonic uint key; 4-pass byte radix select finds threshold key T,
//      strictly-greater count G, tie quota kq = 512 - G
//   3) selected = (u > T) || (u == T && tie_rank_by_index < kq)
//      (identical to jax top_k: among equal values, lower index wins)
//   4) ballot-scan compaction in ascending index order -> selidx
// ---------------------------------------------------------------------------
__global__ void __launch_bounds__(1024) select_kernel(
    const float* __restrict__ partial, int* __restrict__ selidx)
{
    const int b   = blockIdx.x;
    const int j   = threadIdx.x;
    const int wid = j >> 5;
    const int lane = j & 31;

    // ---- 1) reduce partials for column j (coalesced) ----
    float sum = 0.f;
    const float* p = partial + (size_t)b * SPLITS * L + j;
#pragma unroll 12
    for (int s = 0; s < SPLITS; ++s) sum += p[(size_t)s * L];

    // ---- 2) monotonic key ----
    const unsigned ub = __float_as_uint(sum);
    const unsigned u  = ub ^ ((ub & 0x80000000u) ? 0xFFFFFFFFu : 0x80000000u);

    __shared__ int      hist[256];
    __shared__ int      suf[256];
    __shared__ unsigned s_pref;
    __shared__ int      s_k;
    __shared__ int      wcnt[32];
    __shared__ int      woff[32];

    if (j == 0) { s_pref = 0u; s_k = KSEL; }
    __syncthreads();

#pragma unroll
    for (int pass = 0; pass < 4; ++pass) {
        const int shift = 24 - 8 * pass;
        const unsigned pref = s_pref;
        const int kcur = s_k;

        if (j < 256) hist[j] = 0;
        __syncthreads();

        const bool active = (pass == 0) ||
            (((u ^ pref) >> (shift + 8)) == 0u);
        const int byte = (u >> shift) & 0xFF;
        if (active) atomicAdd(&hist[byte], 1);
        __syncthreads();

        if (j < 256) suf[j] = hist[j];
        __syncthreads();
        // inclusive suffix scan: suf[x] = count of active with byte >= x
#pragma unroll
        for (int d = 1; d < 256; d <<= 1) {
            int v = 0;
            if (j < 256 && j + d < 256) v = suf[j + d];
            __syncthreads();
            if (j < 256) suf[j] += v;
            __syncthreads();
        }

        if (j < 256) {
            const int ge = suf[j];
            const int gt = ge - hist[j];
            if (gt < kcur && ge >= kcur) {      // exactly one bin fires
                s_pref = pref | ((unsigned)j << shift);
                s_k    = kcur - gt;             // tie quota carried down
            }
        }
        __syncthreads();
    }

    const unsigned T  = s_pref;   // threshold key (512th-largest)
    const int      kq = s_k;      // slots for ties (>= 1)

    // ---- 3) tie ranking by ascending index ----
    const bool tie = (u == T);
    const unsigned tmask = __ballot_sync(0xffffffffu, tie);
    if (lane == 0) wcnt[wid] = __popc(tmask);
    __syncthreads();
    if (wid == 0) {
        int val = wcnt[lane];
        const int orig = val;
#pragma unroll
        for (int d = 1; d < 32; d <<= 1) {
            const int n = __shfl_up_sync(0xffffffffu, val, d);
            if (lane >= d) val += n;
        }
        woff[lane] = val - orig;   // exclusive prefix
    }
    __syncthreads();
    const int tiepos = woff[wid] + __popc(tmask & ((1u << lane) - 1u));

    const bool sel = (u > T) || (tie && tiepos < kq);
    __syncthreads();  // woff/wcnt reuse below

    // ---- 4) compact selected indices in ascending order ----
    const unsigned smask = __ballot_sync(0xffffffffu, sel);
    if (lane == 0) wcnt[wid] = __popc(smask);
    __syncthreads();
    if (wid == 0) {
        int val = wcnt[lane];
        const int orig = val;
#pragma unroll
        for (int d = 1; d < 32; d <<= 1) {
            const int n = __shfl_up_sync(0xffffffffu, val, d);
            if (lane >= d) val += n;
        }
        woff[lane] = val - orig;
    }
    __syncthreads();

    if (sel) {
        const int pos = woff[wid] + __popc(smask & ((1u << lane) - 1u));
        selidx[b * KSEL + pos] = j;
    }
}

// ---------------------------------------------------------------------------
// Kernel C: gather rows + mask into output. Row 0 = class token (j=0).
// grid (513, B), block 192 (768/4 float4 per row).
// ---------------------------------------------------------------------------
__global__ void __launch_bounds__(192) gather_kernel(
    const float* __restrict__ hs, const float* __restrict__ mask,
    const int* __restrict__ selidx, float* __restrict__ out)
{
    const int r = blockIdx.x;           // 0..512
    const int b = blockIdx.y;
    const int j = (r == 0) ? 0 : selidx[b * KSEL + (r - 1)];

    const float4* src = (const float4*)(hs + ((size_t)b * L + j) * D);
    float4* dst = (float4*)(out + ((size_t)b * (KSEL + 1) + r) * D);
    dst[threadIdx.x] = src[threadIdx.x];

    if (threadIdx.x == 0) {
        const float m = (r == 0) ? 0.f : mask[(size_t)b * L + j];
        out[(size_t)B * (KSEL + 1) * D + (size_t)b * (KSEL + 1) + r] = m;
    }
}

// ---------------------------------------------------------------------------
extern "C" void kernel_launch(void* const* d_in, const int* in_sizes, int n_in,
                              void* d_out, int out_size)
{
    const float* hidden = (const float*)d_in[0];   // [B, L, D]
    const float* amask  = (const float*)d_in[1];   // [B, 1, 1, L]
    const float* scores = (const float*)d_in[2];   // [B, H, L, L]
    float* out = (float*)d_out;                    // tokens then mask, f32

    float* d_partial;
    int*   d_selidx;
    cudaGetSymbolAddress((void**)&d_partial, g_partial);
    cudaGetSymbolAddress((void**)&d_selidx,  g_selidx);

    dim3 gridA(B, SPLITS);
    colsum_kernel<<<gridA, 256>>>((const float4*)scores, (float4*)d_partial);

    select_kernel<<<B, 1024>>>(d_partial, d_selidx);

    dim3 gridC(KSEL + 1, B);
    gather_kernel<<<gridC, 192>>>(hidden, amask, d_selidx, out);
}